// round 5
// baseline (speedup 1.0000x reference)
#include <cuda_runtime.h>

// FoRefLoss: sum over B rows of (dx^2 + dy^2 + wrapped_angle^2), B=8388608.
// Blocked-contiguous variant: each CTA streams one contiguous slab of the
// buffers sequentially (best DRAM row locality). Body stride = 3*256 float4s,
// so the three loads per body have mod-3 residues t, t+1, t+2 -> all angle
// masks are compile-time per thread. __ldcs: streaming / evict-first.
// Angle term in turn-space: t = 2*min(frac(|d|), 1-frac(|d|)), contribution t^2.
// Single kernel; last-arriving block reduces partials in fixed order.

#define NBLOCKS 1024
#define NTHREADS 256

__device__ float g_partials[NBLOCKS];
__device__ unsigned int g_arrived = 0;

__device__ __forceinline__ float vcomp(float p, float l, bool is_angle) {
    float d = p - l;               // difference in "turns" (full circle = 1.0)
    float ad = fabsf(d);
    float f = ad - floorf(ad);     // frac in [0,1)
    float w = fminf(f, 1.0f - f);  // folded to [0, 0.5]
    return is_angle ? (w + w) : d; // angle: 2w = clamped_angle/pi; else diff
}

__device__ __forceinline__ float slot(float4 p, float4 l,
                                      bool aA, bool aB, bool aC, float acc) {
    float v;
    v = vcomp(p.x, l.x, aA); acc = fmaf(v, v, acc);
    v = vcomp(p.y, l.y, aB); acc = fmaf(v, v, acc);
    v = vcomp(p.z, l.z, aC); acc = fmaf(v, v, acc);
    v = vcomp(p.w, l.w, aA); acc = fmaf(v, v, acc);
    return acc;
}

__global__ void __launch_bounds__(NTHREADS)
foref_loss_kernel(const float4* __restrict__ pred,
                  const float4* __restrict__ lab,
                  int n4,                 // total float4 count per tensor
                  float* __restrict__ out)
{
    const int t = threadIdx.x;

    // Each body covers 3*NTHREADS consecutive float4s; each block gets
    // `bodies` consecutive bodies -> contiguous slab per CTA.
    const int bodies = n4 / (3 * NTHREADS * NBLOCKS);   // 8 for n4 = 6291456
    const int chunk  = bodies * 3 * NTHREADS;           // float4s per block

    // float-index of float4 k, comp c is the angle iff (k + c) % 3 == 2.
    // Block base = blockIdx.x * chunk with chunk % 3 == 0, body stride 768 % 3
    // == 0 -> residues of the three loads are (t, t+1, t+2) mod 3: static.
    int m0 = t % 3;
    int m1 = (m0 + 1 == 3) ? 0 : m0 + 1;
    int m2 = (m1 + 1 == 3) ? 0 : m1 + 1;
    const bool A0 = (m0 == 2), B0 = (m0 == 1), C0 = (m0 == 0);
    const bool A1 = (m1 == 2), B1 = (m1 == 1), C1 = (m1 == 0);
    const bool A2 = (m2 == 2), B2 = (m2 == 1), C2 = (m2 == 0);

    float s0 = 0.0f, s1 = 0.0f, s2 = 0.0f;

    int k = blockIdx.x * chunk + t;
    for (int it = 0; it < bodies; ++it) {
        // front-batch 6 independent LDG.128 (streaming, evict-first)
        float4 p0 = __ldcs(pred + k);
        float4 p1 = __ldcs(pred + k +     NTHREADS);
        float4 p2 = __ldcs(pred + k + 2 * NTHREADS);
        float4 l0 = __ldcs(lab  + k);
        float4 l1 = __ldcs(lab  + k +     NTHREADS);
        float4 l2 = __ldcs(lab  + k + 2 * NTHREADS);

        s0 = slot(p0, l0, A0, B0, C0, s0);
        s1 = slot(p1, l1, A1, B1, C1, s1);
        s2 = slot(p2, l2, A2, B2, C2, s2);

        k += 3 * NTHREADS;
    }

    // generic tail for any leftover range (empty for n4 = 6291456)
    for (int kk = NBLOCKS * chunk + blockIdx.x * NTHREADS + t;
         kk < n4; kk += NBLOCKS * NTHREADS) {
        float4 p = pred[kk];
        float4 l = lab[kk];
        int mm = kk % 3;
        s0 = slot(p, l, (mm == 2), (mm == 1), (mm == 0), s0);
    }

    float sum = (s0 + s1) + s2;

    // intra-block reduce
    #pragma unroll
    for (int off = 16; off > 0; off >>= 1)
        sum += __shfl_down_sync(0xFFFFFFFFu, sum, off);

    __shared__ float smem[NTHREADS / 32];
    __shared__ bool is_last;
    int lane = threadIdx.x & 31;
    int wid  = threadIdx.x >> 5;
    if (lane == 0) smem[wid] = sum;
    __syncthreads();

    if (wid == 0) {
        float v = (lane < NTHREADS / 32) ? smem[lane] : 0.0f;
        #pragma unroll
        for (int off = 4; off > 0; off >>= 1)
            v += __shfl_down_sync(0xFFFFFFFFu, v, off);
        if (lane == 0) {
            g_partials[blockIdx.x] = v;
            __threadfence();
            unsigned int a = atomicAdd(&g_arrived, 1u);
            is_last = (a == (unsigned int)(gridDim.x - 1));
        }
    }
    __syncthreads();

    if (is_last) {
        float v = 0.0f;
        for (int i = threadIdx.x; i < NBLOCKS; i += NTHREADS)
            v += g_partials[i];

        #pragma unroll
        for (int off = 16; off > 0; off >>= 1)
            v += __shfl_down_sync(0xFFFFFFFFu, v, off);

        if (lane == 0) smem[wid] = v;
        __syncthreads();

        if (wid == 0) {
            float t2 = (lane < NTHREADS / 32) ? smem[lane] : 0.0f;
            #pragma unroll
            for (int off = 4; off > 0; off >>= 1)
                t2 += __shfl_down_sync(0xFFFFFFFFu, t2, off);
            if (lane == 0) {
                out[0] = t2;
                g_arrived = 0;  // reset for next graph replay
            }
        }
    }
}

extern "C" void kernel_launch(void* const* d_in, const int* in_sizes, int n_in,
                              void* d_out, int out_size)
{
    const float4* pred = (const float4*)d_in[0];
    const float4* lab  = (const float4*)d_in[1];
    float* out = (float*)d_out;

    int n_floats = in_sizes[0];   // 25165824
    int n4 = n_floats / 4;        // 6291456

    foref_loss_kernel<<<NBLOCKS, NTHREADS>>>(pred, lab, n4, out);
}

// round 6
// speedup vs baseline: 1.0130x; 1.0130x over previous
#include <cuda_runtime.h>

// FoRefLoss: sum over B rows of (dx^2 + dy^2 + wrapped_angle^2), B=8388608.
// Champion config (round 3: grid-stride, 1024x256, exactly 24 iters/thread)
// + static angle masks: stride = 262144 == 1 (mod 3), so unroll-3 slots have
// residues m, m+1, m+2 that are invariant across bodies. 6 LDG.128
// front-batched per body (MLP=6), 3 independent accumulators.
// Angle term in turn-space: t = 2*min(frac(|d|), 1-frac(|d|)), contribution t^2.
// Single kernel; last-arriving block reduces partials in fixed order.

#define NBLOCKS 1024
#define NTHREADS 256
#define STRIDE (NBLOCKS * NTHREADS)   // 262144; 262144 % 3 == 1

__device__ float g_partials[NBLOCKS];
__device__ unsigned int g_arrived = 0;

__device__ __forceinline__ float vcomp(float p, float l, bool is_angle) {
    float d = p - l;               // difference in "turns" (full circle = 1.0)
    float ad = fabsf(d);
    float f = ad - floorf(ad);     // frac in [0,1)
    float w = fminf(f, 1.0f - f);  // folded to [0, 0.5]
    return is_angle ? (w + w) : d; // angle: 2w = clamped_angle/pi; else diff
}

__device__ __forceinline__ float slot(float4 p, float4 l,
                                      bool aA, bool aB, bool aC, float acc) {
    float v;
    v = vcomp(p.x, l.x, aA); acc = fmaf(v, v, acc);
    v = vcomp(p.y, l.y, aB); acc = fmaf(v, v, acc);
    v = vcomp(p.z, l.z, aC); acc = fmaf(v, v, acc);
    v = vcomp(p.w, l.w, aA); acc = fmaf(v, v, acc);
    return acc;
}

__global__ void __launch_bounds__(NTHREADS)
foref_loss_kernel(const float4* __restrict__ pred,
                  const float4* __restrict__ lab,
                  int n4,                 // total float4 count per tensor
                  float* __restrict__ out)
{
    int tid0 = blockIdx.x * NTHREADS + threadIdx.x;

    // Residues of the 3 unrolled slots: (k)%3, (k+STRIDE)%3, (k+2*STRIDE)%3.
    // STRIDE % 3 == 1, and one body advances k by 3*STRIDE == 0 (mod 3),
    // so these are constant per thread across all bodies.
    int m0 = tid0 % 3;
    int m1 = (m0 + 1 == 3) ? 0 : m0 + 1;
    int m2 = (m1 + 1 == 3) ? 0 : m1 + 1;
    const bool A0 = (m0 == 2), B0 = (m0 == 1), C0 = (m0 == 0);
    const bool A1 = (m1 == 2), B1 = (m1 == 1), C1 = (m1 == 0);
    const bool A2 = (m2 == 2), B2 = (m2 == 1), C2 = (m2 == 0);

    float s0 = 0.0f, s1 = 0.0f, s2 = 0.0f;

    int bodies = n4 / (3 * STRIDE);   // 8 for n4 = 6291456 (exact)
    int k = tid0;
    for (int it = 0; it < bodies; ++it) {
        // front-batch 6 independent LDG.128 (MLP = 6)
        float4 p0 = pred[k];
        float4 p1 = pred[k +     STRIDE];
        float4 p2 = pred[k + 2 * STRIDE];
        float4 l0 = lab [k];
        float4 l1 = lab [k +     STRIDE];
        float4 l2 = lab [k + 2 * STRIDE];

        s0 = slot(p0, l0, A0, B0, C0, s0);
        s1 = slot(p1, l1, A1, B1, C1, s1);
        s2 = slot(p2, l2, A2, B2, C2, s2);

        k += 3 * STRIDE;
    }
    // generic tail (empty for n4 = 6291456)
    for (; k < n4; k += STRIDE) {
        float4 p = pred[k];
        float4 l = lab[k];
        int mm = k % 3;
        s0 = slot(p, l, (mm == 2), (mm == 1), (mm == 0), s0);
    }

    float sum = (s0 + s1) + s2;

    // intra-block reduce
    #pragma unroll
    for (int off = 16; off > 0; off >>= 1)
        sum += __shfl_down_sync(0xFFFFFFFFu, sum, off);

    __shared__ float smem[NTHREADS / 32];
    __shared__ bool is_last;
    int lane = threadIdx.x & 31;
    int wid  = threadIdx.x >> 5;
    if (lane == 0) smem[wid] = sum;
    __syncthreads();

    if (wid == 0) {
        float v = (lane < NTHREADS / 32) ? smem[lane] : 0.0f;
        #pragma unroll
        for (int off = 4; off > 0; off >>= 1)
            v += __shfl_down_sync(0xFFFFFFFFu, v, off);
        if (lane == 0) {
            g_partials[blockIdx.x] = v;
            __threadfence();
            unsigned int a = atomicAdd(&g_arrived, 1u);
            is_last = (a == (unsigned int)(gridDim.x - 1));
        }
    }
    __syncthreads();

    if (is_last) {
        float v = 0.0f;
        for (int i = threadIdx.x; i < NBLOCKS; i += NTHREADS)
            v += g_partials[i];

        #pragma unroll
        for (int off = 16; off > 0; off >>= 1)
            v += __shfl_down_sync(0xFFFFFFFFu, v, off);

        if (lane == 0) smem[wid] = v;
        __syncthreads();

        if (wid == 0) {
            float t2 = (lane < NTHREADS / 32) ? smem[lane] : 0.0f;
            #pragma unroll
            for (int off = 4; off > 0; off >>= 1)
                t2 += __shfl_down_sync(0xFFFFFFFFu, t2, off);
            if (lane == 0) {
                out[0] = t2;
                g_arrived = 0;  // reset for next graph replay
            }
        }
    }
}

extern "C" void kernel_launch(void* const* d_in, const int* in_sizes, int n_in,
                              void* d_out, int out_size)
{
    const float4* pred = (const float4*)d_in[0];
    const float4* lab  = (const float4*)d_in[1];
    float* out = (float*)d_out;

    int n_floats = in_sizes[0];   // 25165824
    int n4 = n_floats / 4;        // 6291456

    foref_loss_kernel<<<NBLOCKS, NTHREADS>>>(pred, lab, n4, out);
}

// round 7
// speedup vs baseline: 1.0580x; 1.0444x over previous
#include <cuda_runtime.h>

// FoRefLoss: sum over B rows of (dx^2 + dy^2 + wrapped_angle^2), B=8388608.
// Champion configuration (measured best across 6-round experiment matrix):
// grid-stride, 1024x256, compiler-scheduled `#pragma unroll 2`, dynamic
// per-iteration mod-3 angle masks. Coalesced float4 loads (128B/wavefront).
// Angle term in turn-space: t = 2*min(frac(|d|), 1-frac(|d|)), contribution t^2.
// Single kernel; last-arriving block reduces partials in fixed order
// (deterministic: summation order independent of block arrival timing).

#define NBLOCKS 1024
#define NTHREADS 256

__device__ float g_partials[NBLOCKS];
__device__ unsigned int g_arrived = 0;

__device__ __forceinline__ float vcomp(float p, float l, bool is_angle) {
    float d = p - l;              // difference in "turns" (full circle = 1.0)
    float ad = fabsf(d);
    float f = ad - floorf(ad);    // frac in [0,1)
    float w = fminf(f, 1.0f - f); // folded to [0, 0.5]
    return is_angle ? (w + w) : d; // angle: 2w = clamped_angle/pi; else diff
}

__global__ void __launch_bounds__(NTHREADS)
foref_loss_kernel(const float4* __restrict__ pred,
                  const float4* __restrict__ lab,
                  int n4,                 // total float4 count per tensor
                  float* __restrict__ out)
{
    const int stride = NBLOCKS * NTHREADS;      // 262144; 262144 % 3 == 1
    int tid0 = blockIdx.x * NTHREADS + threadIdx.x;

    float sum = 0.0f;
    int iters = n4 / stride;   // 24 exactly for n4 = 6291456

    int k = tid0;
    int m = k % 3;

    #pragma unroll 2
    for (int it = 0; it < iters; ++it) {
        float4 p = pred[k];
        float4 l = lab[k];
        // component c is angle iff (k + c) % 3 == 2
        bool aA = (m == 2);   // c = 0 and c = 3
        bool aB = (m == 1);   // c = 1
        bool aC = (m == 0);   // c = 2
        float v;
        v = vcomp(p.x, l.x, aA); sum = fmaf(v, v, sum);
        v = vcomp(p.y, l.y, aB); sum = fmaf(v, v, sum);
        v = vcomp(p.z, l.z, aC); sum = fmaf(v, v, sum);
        v = vcomp(p.w, l.w, aA); sum = fmaf(v, v, sum);
        k += stride;
        m = (m == 2) ? 0 : (m + 1);   // stride % 3 == 1
    }
    // generic tail (empty for n4 = 6291456)
    if (k < n4) {
        float4 p = pred[k];
        float4 l = lab[k];
        bool aA = (m == 2), aB = (m == 1), aC = (m == 0);
        float v;
        v = vcomp(p.x, l.x, aA); sum = fmaf(v, v, sum);
        v = vcomp(p.y, l.y, aB); sum = fmaf(v, v, sum);
        v = vcomp(p.z, l.z, aC); sum = fmaf(v, v, sum);
        v = vcomp(p.w, l.w, aA); sum = fmaf(v, v, sum);
    }

    // intra-block reduce
    #pragma unroll
    for (int off = 16; off > 0; off >>= 1)
        sum += __shfl_down_sync(0xFFFFFFFFu, sum, off);

    __shared__ float smem[NTHREADS / 32];
    __shared__ bool is_last;
    int lane = threadIdx.x & 31;
    int wid  = threadIdx.x >> 5;
    if (lane == 0) smem[wid] = sum;
    __syncthreads();

    if (wid == 0) {
        float v = (lane < NTHREADS / 32) ? smem[lane] : 0.0f;
        #pragma unroll
        for (int off = 4; off > 0; off >>= 1)
            v += __shfl_down_sync(0xFFFFFFFFu, v, off);
        if (lane == 0) {
            g_partials[blockIdx.x] = v;
            __threadfence();
            unsigned int t = atomicAdd(&g_arrived, 1u);
            is_last = (t == (unsigned int)(gridDim.x - 1));
        }
    }
    __syncthreads();

    if (is_last) {
        // all partials are globally visible now; reduce in fixed order
        float v = 0.0f;
        for (int i = threadIdx.x; i < NBLOCKS; i += NTHREADS)
            v += g_partials[i];

        #pragma unroll
        for (int off = 16; off > 0; off >>= 1)
            v += __shfl_down_sync(0xFFFFFFFFu, v, off);

        if (lane == 0) smem[wid] = v;
        __syncthreads();

        if (wid == 0) {
            float t2 = (lane < NTHREADS / 32) ? smem[lane] : 0.0f;
            #pragma unroll
            for (int off = 4; off > 0; off >>= 1)
                t2 += __shfl_down_sync(0xFFFFFFFFu, t2, off);
            if (lane == 0) {
                out[0] = t2;
                g_arrived = 0;  // reset for next graph replay
            }
        }
    }
}

extern "C" void kernel_launch(void* const* d_in, const int* in_sizes, int n_in,
                              void* d_out, int out_size)
{
    const float4* pred = (const float4*)d_in[0];
    const float4* lab  = (const float4*)d_in[1];
    float* out = (float*)d_out;

    int n_floats = in_sizes[0];   // 25165824
    int n4 = n_floats / 4;        // 6291456

    foref_loss_kernel<<<NBLOCKS, NTHREADS>>>(pred, lab, n4, out);
}